// round 7
// baseline (speedup 1.0000x reference)
#include <cuda_runtime.h>
#include <cuda_bf16.h>

// PackedAvgPool1d: out[t, :] = sum_{i<min(rem[t],K)} x[base[t]+i, :] / min(rem[t],K)
// D = 768 floats per row = 192 float4.
//
// 8 tokens per CTA, 192 threads; thread c owns float4-column c for all 8
// tokens. All 16 row-loads are independent and front-batched (target
// MLP_p1 = 16) — R3 (TPB=4, regs=36) showed ptxas kept < 8 loads live and
// we stalled at 80.4% DRAM. Streaming stores (__stcs): output is never
// re-read.

#define DIM 768
#define CPR (DIM / 4)   // float4 per row = 192
#define TPB 8           // tokens per block

__global__ __launch_bounds__(CPR) void packed_avgpool1d_kernel(
    const float4* __restrict__ x,      // [Tx, CPR]
    const int*    __restrict__ base,   // [Ty]
    const int*    __restrict__ rem,    // [Ty]
    const int*    __restrict__ kptr,   // scalar
    float4*       __restrict__ out,    // [Ty, CPR]
    int Ty)
{
    const int c  = threadIdx.x;
    const int t0 = blockIdx.x * TPB;
    const int K  = __ldg(kptr);

    if (K == 2 && t0 + TPB <= Ty) {
        // Fast path: K=2, full group of 8 tokens.
        int b[TPB], r[TPB];
        #pragma unroll
        for (int u = 0; u < TPB; ++u) {
            b[u] = __ldg(&base[t0 + u]);
            r[u] = __ldg(&rem[t0 + u]);
        }

        // Front-batch all 16 independent row loads.
        float4 v0[TPB], v1[TPB];
        #pragma unroll
        for (int u = 0; u < TPB; ++u)
            v0[u] = __ldg(&x[(long long)b[u] * CPR + c]);
        #pragma unroll
        for (int u = 0; u < TPB; ++u) {
            if (r[u] > 1) {
                v1[u] = __ldg(&x[(long long)(b[u] + 1) * CPR + c]);
            } else {
                v1[u] = make_float4(0.f, 0.f, 0.f, 0.f);
            }
        }

        #pragma unroll
        for (int u = 0; u < TPB; ++u) {
            const float inv = (r[u] > 1) ? 0.5f : 1.0f;
            float4 o;
            o.x = (v0[u].x + v1[u].x) * inv;
            o.y = (v0[u].y + v1[u].y) * inv;
            o.z = (v0[u].z + v1[u].z) * inv;
            o.w = (v0[u].w + v1[u].w) * inv;
            __stcs(&out[(long long)(t0 + u) * CPR + c], o);
        }
    } else {
        // Generic / tail path: arbitrary K, partial group.
        for (int u = 0; u < TPB; ++u) {
            const int t = t0 + u;
            if (t >= Ty) break;
            const int b = __ldg(&base[t]);
            const int r = __ldg(&rem[t]);

            float4 acc = make_float4(0.f, 0.f, 0.f, 0.f);
            for (int k = 0; k < K; ++k) {
                if (k < r) {
                    float4 v = __ldg(&x[(long long)(b + k) * CPR + c]);
                    acc.x += v.x; acc.y += v.y; acc.z += v.z; acc.w += v.w;
                }
            }
            const int cnt = min(r, K);          // >= 1 by construction
            const float inv = 1.0f / (float)cnt;
            acc.x *= inv; acc.y *= inv; acc.z *= inv; acc.w *= inv;
            __stcs(&out[(long long)t * CPR + c], acc);
        }
    }
}

extern "C" void kernel_launch(void* const* d_in, const int* in_sizes, int n_in,
                              void* d_out, int out_size)
{
    const float4* x    = (const float4*)d_in[0];
    const int*    base = (const int*)d_in[1];
    const int*    rem  = (const int*)d_in[2];
    const int*    kptr = (const int*)d_in[3];
    float4*       out  = (float4*)d_out;

    const int Ty = in_sizes[1];   // one entry per output token
    const int nblk = (Ty + TPB - 1) / TPB;

    packed_avgpool1d_kernel<<<nblk, CPR>>>(x, base, rem, kptr, out, Ty);
}

// round 8
// speedup vs baseline: 1.0746x; 1.0746x over previous
#include <cuda_runtime.h>
#include <cuda_bf16.h>

// PackedAvgPool1d: out[t, :] = sum_{i<min(rem[t],K)} x[base[t]+i, :] / min(rem[t],K)
// D = 768 floats per row = 192 float4.
//
// TPB=4 (the R3 sweet spot: 8 live float4 = 32 regs fits the default reg
// budget; TPB=8 made ptxas serialize the batch and regressed).
// Change vs R3: second-row loads are UNCONDITIONAL with a clamped index
// (min(b+1, Tx-1)) so all 8 LDGs issue as one unpredicated back-to-back
// batch; the rem-mask is applied arithmetically afterwards.

#define DIM 768
#define CPR (DIM / 4)   // float4 per row = 192
#define TPB 4           // tokens per block

__global__ __launch_bounds__(CPR, 8) void packed_avgpool1d_kernel(
    const float4* __restrict__ x,      // [Tx, CPR]
    const int*    __restrict__ base,   // [Ty]
    const int*    __restrict__ rem,    // [Ty]
    const int*    __restrict__ kptr,   // scalar
    float4*       __restrict__ out,    // [Ty, CPR]
    int Ty, int Tx)
{
    const int c  = threadIdx.x;
    const int t0 = blockIdx.x * TPB;
    const int K  = __ldg(kptr);

    if (K == 2 && t0 + TPB <= Ty) {
        // Fast path: K=2, full group of 4 tokens.
        int b[TPB], r[TPB];
        #pragma unroll
        for (int u = 0; u < TPB; ++u) {
            b[u] = __ldg(&base[t0 + u]);
            r[u] = __ldg(&rem[t0 + u]);
        }

        // Front-batch all 8 row loads, unpredicated. Second row index is
        // clamped so the load is always in-bounds; its value is discarded
        // arithmetically when rem <= 1.
        float4 v0[TPB], v1[TPB];
        #pragma unroll
        for (int u = 0; u < TPB; ++u)
            v0[u] = __ldg(&x[(long long)b[u] * CPR + c]);
        #pragma unroll
        for (int u = 0; u < TPB; ++u) {
            const int b1 = min(b[u] + 1, Tx - 1);
            v1[u] = __ldg(&x[(long long)b1 * CPR + c]);
        }

        #pragma unroll
        for (int u = 0; u < TPB; ++u) {
            const bool two = (r[u] > 1);
            const float w1  = two ? 1.0f : 0.0f;   // include second row?
            const float inv = two ? 0.5f : 1.0f;
            float4 o;
            o.x = (v0[u].x + w1 * v1[u].x) * inv;
            o.y = (v0[u].y + w1 * v1[u].y) * inv;
            o.z = (v0[u].z + w1 * v1[u].z) * inv;
            o.w = (v0[u].w + w1 * v1[u].w) * inv;
            out[(long long)(t0 + u) * CPR + c] = o;
        }
    } else {
        // Generic / tail path: arbitrary K, partial group.
        for (int u = 0; u < TPB; ++u) {
            const int t = t0 + u;
            if (t >= Ty) break;
            const int b = __ldg(&base[t]);
            const int r = __ldg(&rem[t]);

            float4 acc = make_float4(0.f, 0.f, 0.f, 0.f);
            for (int k = 0; k < K; ++k) {
                if (k < r) {
                    float4 v = __ldg(&x[(long long)(b + k) * CPR + c]);
                    acc.x += v.x; acc.y += v.y; acc.z += v.z; acc.w += v.w;
                }
            }
            const int cnt = min(r, K);          // >= 1 by construction
            const float inv = 1.0f / (float)cnt;
            acc.x *= inv; acc.y *= inv; acc.z *= inv; acc.w *= inv;
            out[(long long)t * CPR + c] = acc;
        }
    }
}

extern "C" void kernel_launch(void* const* d_in, const int* in_sizes, int n_in,
                              void* d_out, int out_size)
{
    const float4* x    = (const float4*)d_in[0];
    const int*    base = (const int*)d_in[1];
    const int*    rem  = (const int*)d_in[2];
    const int*    kptr = (const int*)d_in[3];
    float4*       out  = (float4*)d_out;

    const int Ty = in_sizes[1];          // one entry per output token
    const int Tx = in_sizes[0] / DIM;    // input rows
    const int nblk = (Ty + TPB - 1) / TPB;

    packed_avgpool1d_kernel<<<nblk, CPR>>>(x, base, rem, kptr, out, Ty, Tx);
}